// round 7
// baseline (speedup 1.0000x reference)
#include <cuda_runtime.h>
#include <cuda_bf16.h>
#include <math.h>
#include <stdint.h>

#define T_TOK 2048
#define HDIM  1024
#define FDIM  512
#define NE    32
#define TOPK  4
#define SLOTS (T_TOK * TOPK)

// ---------------- scratch ----------------
__device__ int   g_cnt[NE];
__device__ int   g_base[NE];
__device__ int   g_btok[NE * T_TOK];
__device__ float g_bw  [NE * T_TOK];
__device__ int   g_pe  [T_TOK * TOPK];
__device__ int   g_pp  [T_TOK * TOPK];
__device__ __nv_bfloat16 g_hhi[(size_t)SLOTS * FDIM];   // 8 MB
__device__ __nv_bfloat16 g_hlo[(size_t)SLOTS * FDIM];   // 8 MB
__device__ float g_ybuf[(size_t)SLOTS * HDIM];          // 32 MB
__device__ __nv_bfloat16 g_xh [(size_t)T_TOK * HDIM];   // 4 MB
__device__ __nv_bfloat16 g_xl [(size_t)T_TOK * HDIM];   // 4 MB

// ---------------- helpers ----------------
__device__ __forceinline__ void mma16816(float* d, const uint32_t* a, const uint32_t* b) {
    asm volatile(
        "mma.sync.aligned.m16n8k16.row.col.f32.bf16.bf16.f32 "
        "{%0,%1,%2,%3}, {%4,%5,%6,%7}, {%8,%9}, {%0,%1,%2,%3};\n"
        : "+f"(d[0]), "+f"(d[1]), "+f"(d[2]), "+f"(d[3])
        : "r"(a[0]), "r"(a[1]), "r"(a[2]), "r"(a[3]), "r"(b[0]), "r"(b[1]));
}

__device__ __forceinline__ void split2(float a, float b, uint32_t& h, uint32_t& l) {
    __nv_bfloat162 hh = __floats2bfloat162_rn(a, b);
    float2 hf = __bfloat1622float2(hh);
    __nv_bfloat162 ll = __floats2bfloat162_rn(a - hf.x, b - hf.y);
    h = *reinterpret_cast<uint32_t*>(&hh);
    l = *reinterpret_cast<uint32_t*>(&ll);
}
__device__ __forceinline__ void split4(float4 v, uint2& hv, uint2& lv) {
    split2(v.x, v.y, hv.x, lv.x);
    split2(v.z, v.w, hv.y, lv.y);
}
__device__ __forceinline__ void split8(const float* x, uint4& hv, uint4& lv) {
    uint32_t h[4], l[4];
#pragma unroll
    for (int i = 0; i < 4; i++) split2(x[2*i], x[2*i+1], h[i], l[i]);
    hv = make_uint4(h[0], h[1], h[2], h[3]);
    lv = make_uint4(l[0], l[1], l[2], l[3]);
}

__device__ __forceinline__ uint32_t smem_u32(const void* p) {
    uint32_t a;
    asm("{ .reg .u64 t; cvta.to.shared.u64 t, %1; cvt.u32.u64 %0, t; }" : "=r"(a) : "l"(p));
    return a;
}
__device__ __forceinline__ void cpa16(uint32_t dst, const void* src) {
    asm volatile("cp.async.cg.shared.global [%0], [%1], 16;" :: "r"(dst), "l"(src));
}
#define CP_COMMIT() asm volatile("cp.async.commit_group;" ::: "memory")
template<int N> __device__ __forceinline__ void cp_wait() {
    asm volatile("cp.async.wait_group %0;" :: "n"(N) : "memory");
}

// ---------------- X conversion ----------------
__global__ void convert_split(const float* __restrict__ src,
                              __nv_bfloat16* __restrict__ dh,
                              __nv_bfloat16* __restrict__ dl, int n8) {
    int i = blockIdx.x * blockDim.x + threadIdx.x;
    if (i >= n8) return;
    float x[8];
    *(float4*)&x[0] = *(const float4*)(src + 8*(size_t)i);
    *(float4*)&x[4] = *(const float4*)(src + 8*(size_t)i + 4);
    uint4 hv, lv; split8(x, hv, lv);
    *(uint4*)(dh + 8*(size_t)i) = hv;
    *(uint4*)(dl + 8*(size_t)i) = lv;
}

// ---------------- router GEMM ----------------
__global__ void router_gemm(const float* __restrict__ xr, const float* __restrict__ wr,
                            float* __restrict__ logits) {
    __shared__ float Xs[16][68];
    __shared__ float Ws[16][36];
    int tid = threadIdx.x;
    int t0  = blockIdx.x * 64;
    int tx = tid & 31, ty = tid >> 5;
    float acc[8];
#pragma unroll
    for (int j = 0; j < 8; j++) acc[j] = 0.f;
    int mL = tid >> 2, ksL = tid & 3;
    for (int k0 = 0; k0 < HDIM; k0 += 16) {
        float4 v = *(const float4*)(xr + (size_t)(t0 + mL) * HDIM + k0 + ksL * 4);
        Xs[ksL*4+0][mL] = v.x; Xs[ksL*4+1][mL] = v.y;
        Xs[ksL*4+2][mL] = v.z; Xs[ksL*4+3][mL] = v.w;
        if (tid < 128) {
            int n = tid >> 2, ks = tid & 3;
            float4 w = *(const float4*)(wr + (size_t)n * HDIM + k0 + ks * 4);
            Ws[ks*4+0][n] = w.x; Ws[ks*4+1][n] = w.y;
            Ws[ks*4+2][n] = w.z; Ws[ks*4+3][n] = w.w;
        }
        __syncthreads();
#pragma unroll
        for (int kk = 0; kk < 16; kk++) {
            float b = Ws[kk][tx];
            float4 a0 = *(const float4*)&Xs[kk][ty*8];
            float4 a1 = *(const float4*)&Xs[kk][ty*8+4];
            acc[0] += a0.x*b; acc[1] += a0.y*b; acc[2] += a0.z*b; acc[3] += a0.w*b;
            acc[4] += a1.x*b; acc[5] += a1.y*b; acc[6] += a1.z*b; acc[7] += a1.w*b;
        }
        __syncthreads();
    }
#pragma unroll
    for (int j = 0; j < 8; j++)
        logits[(size_t)(t0 + ty*8 + j) * NE + tx] = acc[j];
}

__global__ void zero_cnt() { if (threadIdx.x < NE) g_cnt[threadIdx.x] = 0; }

__global__ void topk_kernel(const float* __restrict__ logits) {
    int t = blockIdx.x * blockDim.x + threadIdx.x;
    if (t >= T_TOK) return;
    float v[NE];
#pragma unroll
    for (int e = 0; e < NE; e++) v[e] = logits[(size_t)t * NE + e];
    float val[TOPK]; int sel[TOPK];
#pragma unroll
    for (int kk = 0; kk < TOPK; kk++) {
        float best = -INFINITY; int bi = 0;
#pragma unroll
        for (int e = 0; e < NE; e++)
            if (v[e] > best) { best = v[e]; bi = e; }
        val[kk] = best; sel[kk] = bi; v[bi] = -INFINITY;
    }
    float mx = val[0];
    float w[TOPK], s = 0.f;
#pragma unroll
    for (int kk = 0; kk < TOPK; kk++) { w[kk] = expf(val[kk] - mx); s += w[kk]; }
    float inv = 1.f / s;
#pragma unroll
    for (int kk = 0; kk < TOPK; kk++) {
        int e = sel[kk];
        int pos = atomicAdd(&g_cnt[e], 1);
        g_btok[e * T_TOK + pos] = t;
        g_bw  [e * T_TOK + pos] = w[kk] * inv;
        g_pe[t * TOPK + kk] = e;
        g_pp[t * TOPK + kk] = pos;
    }
}

__global__ void prefix_kernel() {
    if (threadIdx.x == 0) {
        int s = 0;
        for (int e = 0; e < NE; e++) { g_base[e] = s; s += g_cnt[e]; }
    }
}

// ================= gate/up HMMA kernel =================
// CTA: 256 tokens x 64 F-cols, 512 threads, 16 warps (wm=wid&7, wn=wid>>3).
// BK=32. X (bf16 hi/lo) cp.async 2-stage; W fp32 register-prefetch + in-kernel split.
// SMEM: X stages [0, 40960): hi 0..20480, lo 20480..40960 (pitch 80B); stage2 at 40960.
//       W at 81920: Gh +0, Gl +5120, Uh +10240, Ul +15360. total 102400.
#define PADK 40
#define XSTG 40960
#define GU_SMEM 102400
#define DN_SMEM 92160
__global__ void __launch_bounds__(512, 1) gateup_mma(
        const float* __restrict__ wg, const float* __restrict__ wu) {
    int e   = blockIdx.z;
    int cnt = g_cnt[e];
    int m0  = blockIdx.y * 256;
    if (m0 >= cnt) return;
    int f0 = blockIdx.x * 64;

    extern __shared__ __align__(128) char smem[];
    uint32_t sb = smem_u32(smem);

    int tid = threadIdx.x, wid = tid >> 5, lane = tid & 31;
    int wm = wid & 7, wn = wid >> 3;
    int g = lane >> 2, q = lane & 3;

    // X loader role: 256 rows, hi+lo, 2 half-rows per thread pair
    int xrow = tid >> 1, xhalf = tid & 1;
    int tokL = g_btok[e * T_TOK + min(m0 + xrow, cnt - 1)];
    const __nv_bfloat16* xhs = g_xh + (size_t)tokL * HDIM + xhalf * 16;
    const __nv_bfloat16* xls = g_xl + (size_t)tokL * HDIM + xhalf * 16;
    uint32_t xdst = sb + (uint32_t)xrow * 80 + (uint32_t)xhalf * 32;

    // W loader role: 64 rows x 8 segs of 4 fp32
    int wrow = tid >> 3, wseg = tid & 7;
    const float* gsrc = wg + (size_t)e * FDIM * HDIM + (size_t)(f0 + wrow) * HDIM + wseg * 4;
    const float* usrc = wu + (size_t)e * FDIM * HDIM + (size_t)(f0 + wrow) * HDIM + wseg * 4;
    uint32_t wdst = sb + 81920 + (uint32_t)wrow * 80 + (uint32_t)wseg * 8;

    float accG[2][4][4] = {}, accU[2][4][4] = {};

    const int NC = HDIM / 32;
    // prefetch chunk 0
    float4 gcur = *(const float4*)(gsrc);
    float4 ucur = *(const float4*)(usrc);
    cpa16(xdst, xhs); cpa16(xdst + 16, xhs + 8);
    cpa16(xdst + 20480, xls); cpa16(xdst + 20480 + 16, xls + 8);
    CP_COMMIT();

    for (int ci = 0; ci < NC; ci++) {
        float4 gnxt, unxt;
        if (ci + 1 < NC) {
            int kk = (ci + 1) * 32;
            uint32_t so = ((ci + 1) & 1) * XSTG;
            cpa16(xdst + so, xhs + kk); cpa16(xdst + so + 16, xhs + kk + 8);
            cpa16(xdst + so + 20480, xls + kk); cpa16(xdst + so + 20480 + 16, xls + kk + 8);
            CP_COMMIT();
            gnxt = *(const float4*)(gsrc + kk);
            unxt = *(const float4*)(usrc + kk);
        }
        // convert current W regs -> smem (prev MMA done per trailing sync)
        {
            uint2 hv, lv;
            split4(gcur, hv, lv);
            *(uint2*)(smem + (wdst - sb))         = hv;
            *(uint2*)(smem + (wdst - sb) + 5120)  = lv;
            split4(ucur, hv, lv);
            *(uint2*)(smem + (wdst - sb) + 10240) = hv;
            *(uint2*)(smem + (wdst - sb) + 15360) = lv;
        }
        if (ci + 1 < NC) cp_wait<1>(); else cp_wait<0>();
        __syncthreads();

        const char* st = smem + (ci & 1) * XSTG;
        const __nv_bfloat16* sXh = (const __nv_bfloat16*)(st);
        const __nv_bfloat16* sXl = (const __nv_bfloat16*)(st + 20480);
        const __nv_bfloat16* sGh = (const __nv_bfloat16*)(smem + 81920);
        const __nv_bfloat16* sGl = (const __nv_bfloat16*)(smem + 81920 + 5120);
        const __nv_bfloat16* sUh = (const __nv_bfloat16*)(smem + 81920 + 10240);
        const __nv_bfloat16* sUl = (const __nv_bfloat16*)(smem + 81920 + 15360);

#pragma unroll
        for (int kt = 0; kt < 2; kt++) {
            int kc = kt * 16 + 2 * q;
            uint32_t axh[2][4], axl[2][4];
#pragma unroll
            for (int mt = 0; mt < 2; mt++) {
                int r = wm * 32 + mt * 16 + g;
                axh[mt][0] = *(const uint32_t*)&sXh[r*PADK + kc];
                axh[mt][1] = *(const uint32_t*)&sXh[(r+8)*PADK + kc];
                axh[mt][2] = *(const uint32_t*)&sXh[r*PADK + kc + 8];
                axh[mt][3] = *(const uint32_t*)&sXh[(r+8)*PADK + kc + 8];
                axl[mt][0] = *(const uint32_t*)&sXl[r*PADK + kc];
                axl[mt][1] = *(const uint32_t*)&sXl[(r+8)*PADK + kc];
                axl[mt][2] = *(const uint32_t*)&sXl[r*PADK + kc + 8];
                axl[mt][3] = *(const uint32_t*)&sXl[(r+8)*PADK + kc + 8];
            }
#pragma unroll
            for (int nt = 0; nt < 4; nt++) {
                int br = wn * 32 + nt * 8 + g;
                uint32_t bgh[2] = {*(const uint32_t*)&sGh[br*PADK + kc], *(const uint32_t*)&sGh[br*PADK + kc + 8]};
                uint32_t bgl[2] = {*(const uint32_t*)&sGl[br*PADK + kc], *(const uint32_t*)&sGl[br*PADK + kc + 8]};
                uint32_t buh[2] = {*(const uint32_t*)&sUh[br*PADK + kc], *(const uint32_t*)&sUh[br*PADK + kc + 8]};
                uint32_t bul[2] = {*(const uint32_t*)&sUl[br*PADK + kc], *(const uint32_t*)&sUl[br*PADK + kc + 8]};
#pragma unroll
                for (int mt = 0; mt < 2; mt++) {
                    mma16816(accG[mt][nt], axh[mt], bgh);
                    mma16816(accG[mt][nt], axl[mt], bgh);
                    mma16816(accG[mt][nt], axh[mt], bgl);
                    mma16816(accU[mt][nt], axh[mt], buh);
                    mma16816(accU[mt][nt], axl[mt], buh);
                    mma16816(accU[mt][nt], axh[mt], bul);
                }
            }
        }
        __syncthreads();
        gcur = gnxt; ucur = unxt;
    }

    // epilogue: h = relu(G)*U, write bf16 hi/lo
    int base = g_base[e];
#pragma unroll
    for (int mt = 0; mt < 2; mt++) {
        int lm0 = wm * 32 + mt * 16 + g;
#pragma unroll
        for (int nt = 0; nt < 4; nt++) {
            int c = f0 + wn * 32 + nt * 8 + 2 * q;
            float* Gd = accG[mt][nt];
            float* Ud = accU[mt][nt];
            float v0 = fmaxf(Gd[0], 0.f) * Ud[0];
            float v1 = fmaxf(Gd[1], 0.f) * Ud[1];
            float v2 = fmaxf(Gd[2], 0.f) * Ud[2];
            float v3 = fmaxf(Gd[3], 0.f) * Ud[3];
            uint32_t h01, l01, h23, l23;
            split2(v0, v1, h01, l01);
            split2(v2, v3, h23, l23);
            int m = m0 + lm0;
            if (m < cnt) {
                size_t slot = (size_t)base + m;
                *(uint32_t*)(g_hhi + slot * FDIM + c) = h01;
                *(uint32_t*)(g_hlo + slot * FDIM + c) = l01;
            }
            if (m + 8 < cnt) {
                size_t slot = (size_t)base + m + 8;
                *(uint32_t*)(g_hhi + slot * FDIM + c) = h23;
                *(uint32_t*)(g_hlo + slot * FDIM + c) = l23;
            }
        }
    }
}

// ================= down HMMA kernel =================
// CTA: 256 slots x 64 H-cols, 512 threads. X = h (bf16 hi/lo) cp.async; W fp32 reg-prefetch.
// SMEM: X stages [0, 81920); W at 81920: Wh +0, Wl +5120. total 92160.
__global__ void __launch_bounds__(512, 1) down_mma(const float* __restrict__ wd) {
    int e   = blockIdx.z;
    int cnt = g_cnt[e];
    int m0  = blockIdx.y * 256;
    if (m0 >= cnt) return;
    int h0 = blockIdx.x * 64;

    extern __shared__ __align__(128) char smem[];
    uint32_t sb = smem_u32(smem);

    int tid = threadIdx.x, wid = tid >> 5, lane = tid & 31;
    int wm = wid & 7, wn = wid >> 3;
    int g = lane >> 2, q = lane & 3;
    int base = g_base[e];

    int xrow = tid >> 1, xhalf = tid & 1;
    size_t slotR = (size_t)base + min(m0 + xrow, cnt - 1);
    const __nv_bfloat16* xhs = g_hhi + slotR * FDIM + xhalf * 16;
    const __nv_bfloat16* xls = g_hlo + slotR * FDIM + xhalf * 16;
    uint32_t xdst = sb + (uint32_t)xrow * 80 + (uint32_t)xhalf * 32;

    int wrow = tid >> 3, wseg = tid & 7;
    const float* wsrc = wd + (size_t)e * HDIM * FDIM + (size_t)(h0 + wrow) * FDIM + wseg * 4;
    uint32_t wdst = sb + 81920 + (uint32_t)wrow * 80 + (uint32_t)wseg * 8;

    float acc[2][4][4] = {};

    const int NC = FDIM / 32;
    float4 wcur = *(const float4*)(wsrc);
    cpa16(xdst, xhs); cpa16(xdst + 16, xhs + 8);
    cpa16(xdst + 20480, xls); cpa16(xdst + 20480 + 16, xls + 8);
    CP_COMMIT();

    for (int ci = 0; ci < NC; ci++) {
        float4 wnxt;
        if (ci + 1 < NC) {
            int kk = (ci + 1) * 32;
            uint32_t so = ((ci + 1) & 1) * XSTG;
            cpa16(xdst + so, xhs + kk); cpa16(xdst + so + 16, xhs + kk + 8);
            cpa16(xdst + so + 20480, xls + kk); cpa16(xdst + so + 20480 + 16, xls + kk + 8);
            CP_COMMIT();
            wnxt = *(const float4*)(wsrc + kk);
        }
        {
            uint2 hv, lv;
            split4(wcur, hv, lv);
            *(uint2*)(smem + (wdst - sb))        = hv;
            *(uint2*)(smem + (wdst - sb) + 5120) = lv;
        }
        if (ci + 1 < NC) cp_wait<1>(); else cp_wait<0>();
        __syncthreads();

        const char* st = smem + (ci & 1) * XSTG;
        const __nv_bfloat16* sXh = (const __nv_bfloat16*)(st);
        const __nv_bfloat16* sXl = (const __nv_bfloat16*)(st + 20480);
        const __nv_bfloat16* sWh = (const __nv_bfloat16*)(smem + 81920);
        const __nv_bfloat16* sWl = (const __nv_bfloat16*)(smem + 81920 + 5120);

#pragma unroll
        for (int kt = 0; kt < 2; kt++) {
            int kc = kt * 16 + 2 * q;
            uint32_t axh[2][4], axl[2][4];
#pragma unroll
            for (int mt = 0; mt < 2; mt++) {
                int r = wm * 32 + mt * 16 + g;
                axh[mt][0] = *(const uint32_t*)&sXh[r*PADK + kc];
                axh[mt][1] = *(const uint32_t*)&sXh[(r+8)*PADK + kc];
                axh[mt][2] = *(const uint32_t*)&sXh[r*PADK + kc + 8];
                axh[mt][3] = *(const uint32_t*)&sXh[(r+8)*PADK + kc + 8];
                axl[mt][0] = *(const uint32_t*)&sXl[r*PADK + kc];
                axl[mt][1] = *(const uint32_t*)&sXl[(r+8)*PADK + kc];
                axl[mt][2] = *(const uint32_t*)&sXl[r*PADK + kc + 8];
                axl[mt][3] = *(const uint32_t*)&sXl[(r+8)*PADK + kc + 8];
            }
#pragma unroll
            for (int nt = 0; nt < 4; nt++) {
                int br = wn * 32 + nt * 8 + g;
                uint32_t bwh[2] = {*(const uint32_t*)&sWh[br*PADK + kc], *(const uint32_t*)&sWh[br*PADK + kc + 8]};
                uint32_t bwl[2] = {*(const uint32_t*)&sWl[br*PADK + kc], *(const uint32_t*)&sWl[br*PADK + kc + 8]};
#pragma unroll
                for (int mt = 0; mt < 2; mt++) {
                    mma16816(acc[mt][nt], axh[mt], bwh);
                    mma16816(acc[mt][nt], axl[mt], bwh);
                    mma16816(acc[mt][nt], axh[mt], bwl);
                }
            }
        }
        __syncthreads();
        wcur = wnxt;
    }

    // epilogue: y = acc * routing weight
#pragma unroll
    for (int mt = 0; mt < 2; mt++) {
        int lm0 = wm * 32 + mt * 16 + g;
        int m = m0 + lm0;
        float w0 = (m     < cnt) ? g_bw[e * T_TOK + m]     : 0.f;
        float w1 = (m + 8 < cnt) ? g_bw[e * T_TOK + m + 8] : 0.f;
#pragma unroll
        for (int nt = 0; nt < 4; nt++) {
            int c = h0 + wn * 32 + nt * 8 + 2 * q;
            float* D = acc[mt][nt];
            if (m < cnt) {
                float* py = g_ybuf + ((size_t)base + m) * HDIM + c;
                py[0] = D[0] * w0; py[1] = D[1] * w0;
            }
            if (m + 8 < cnt) {
                float* py = g_ybuf + ((size_t)base + m + 8) * HDIM + c;
                py[0] = D[2] * w1; py[1] = D[3] * w1;
            }
        }
    }
}

// ---------------- combine ----------------
__global__ void combine_kernel(float* __restrict__ out) {
    int t   = blockIdx.x;
    int tid = threadIdx.x;
    int sl[TOPK];
#pragma unroll
    for (int kk = 0; kk < TOPK; kk++)
        sl[kk] = g_base[g_pe[t*TOPK + kk]] + g_pp[t*TOPK + kk];
    int h = tid * 4;
    float4 a = *(const float4*)(g_ybuf + (size_t)sl[0] * HDIM + h);
    float4 b = *(const float4*)(g_ybuf + (size_t)sl[1] * HDIM + h);
    float4 c = *(const float4*)(g_ybuf + (size_t)sl[2] * HDIM + h);
    float4 d = *(const float4*)(g_ybuf + (size_t)sl[3] * HDIM + h);
    float4 r;
    r.x = a.x + b.x + c.x + d.x;
    r.y = a.y + b.y + c.y + d.y;
    r.z = a.z + b.z + c.z + d.z;
    r.w = a.w + b.w + c.w + d.w;
    *(float4*)(out + (size_t)t * HDIM + h) = r;
}

// ---------------- launch ----------------
extern "C" void kernel_launch(void* const* d_in, const int* in_sizes, int n_in,
                              void* d_out, int out_size) {
    const float* router_input = (const float*)d_in[0];
    const float* hidden       = (const float*)d_in[1];
    const float* w_router     = (const float*)d_in[2];
    const float* w_gate       = (const float*)d_in[3];
    const float* w_up         = (const float*)d_in[4];
    const float* w_down       = (const float*)d_in[5];
    float* out    = (float*)d_out;
    float* logits = out + (size_t)T_TOK * HDIM;

    static int attr_done = 0;
    if (!attr_done) {
        cudaFuncSetAttribute(gateup_mma, cudaFuncAttributeMaxDynamicSharedMemorySize, GU_SMEM);
        cudaFuncSetAttribute(down_mma,   cudaFuncAttributeMaxDynamicSharedMemorySize, DN_SMEM);
        attr_done = 1;
    }

    __nv_bfloat16 *xh, *xl;
    cudaGetSymbolAddress((void**)&xh, g_xh);
    cudaGetSymbolAddress((void**)&xl, g_xl);

    const int XN8 = T_TOK * HDIM / 8;
    convert_split<<<XN8 / 256, 256>>>(hidden, xh, xl, XN8);

    zero_cnt<<<1, 32>>>();
    router_gemm<<<T_TOK / 64, 256>>>(router_input, w_router, logits);
    topk_kernel<<<T_TOK / 256, 256>>>(logits);
    prefix_kernel<<<1, 32>>>();
    gateup_mma<<<dim3(FDIM / 64, T_TOK / 256, NE), 512, GU_SMEM>>>(w_gate, w_up);
    down_mma<<<dim3(HDIM / 64, T_TOK / 256, NE), 512, DN_SMEM>>>(w_down);
    combine_kernel<<<T_TOK, 256>>>(out);
}

// round 8
// speedup vs baseline: 1.1645x; 1.1645x over previous
#include <cuda_runtime.h>
#include <cuda_bf16.h>
#include <math.h>
#include <stdint.h>

#define T_TOK 2048
#define HDIM  1024
#define FDIM  512
#define NE    32
#define TOPK  4
#define SLOTS (T_TOK * TOPK)

// ---------------- scratch ----------------
__device__ int   g_cnt[NE];
__device__ int   g_base[NE];
__device__ int   g_btok[NE * T_TOK];
__device__ float g_bw  [NE * T_TOK];
__device__ int   g_pe  [T_TOK * TOPK];
__device__ int   g_pp  [T_TOK * TOPK];
__device__ __nv_bfloat16 g_hhi[(size_t)SLOTS * FDIM];   // 8 MB
__device__ __nv_bfloat16 g_hlo[(size_t)SLOTS * FDIM];   // 8 MB
__device__ float g_ybuf[(size_t)SLOTS * HDIM];          // 32 MB
__device__ __nv_bfloat16 g_xh [(size_t)T_TOK * HDIM];   // 4 MB
__device__ __nv_bfloat16 g_xl [(size_t)T_TOK * HDIM];   // 4 MB

// ---------------- helpers ----------------
__device__ __forceinline__ void mma16816(float* d, const uint32_t* a, const uint32_t* b) {
    asm volatile(
        "mma.sync.aligned.m16n8k16.row.col.f32.bf16.bf16.f32 "
        "{%0,%1,%2,%3}, {%4,%5,%6,%7}, {%8,%9}, {%0,%1,%2,%3};\n"
        : "+f"(d[0]), "+f"(d[1]), "+f"(d[2]), "+f"(d[3])
        : "r"(a[0]), "r"(a[1]), "r"(a[2]), "r"(a[3]), "r"(b[0]), "r"(b[1]));
}

__device__ __forceinline__ void split2(float a, float b, uint32_t& h, uint32_t& l) {
    __nv_bfloat162 hh = __floats2bfloat162_rn(a, b);
    float2 hf = __bfloat1622float2(hh);
    __nv_bfloat162 ll = __floats2bfloat162_rn(a - hf.x, b - hf.y);
    h = *reinterpret_cast<uint32_t*>(&hh);
    l = *reinterpret_cast<uint32_t*>(&ll);
}

// split 8 fp32 -> two uint4 (bf16 hi, bf16 lo)
__device__ __forceinline__ void split8(const float* x, uint4& hv, uint4& lv) {
    uint32_t h[4], l[4];
#pragma unroll
    for (int i = 0; i < 4; i++) split2(x[2*i], x[2*i+1], h[i], l[i]);
    hv = make_uint4(h[0], h[1], h[2], h[3]);
    lv = make_uint4(l[0], l[1], l[2], l[3]);
}

// ---------------- X conversion ----------------
__global__ void convert_split(const float* __restrict__ src,
                              __nv_bfloat16* __restrict__ dh,
                              __nv_bfloat16* __restrict__ dl, int n8) {
    int i = blockIdx.x * blockDim.x + threadIdx.x;
    if (i >= n8) return;
    float x[8];
    *(float4*)&x[0] = *(const float4*)(src + 8*(size_t)i);
    *(float4*)&x[4] = *(const float4*)(src + 8*(size_t)i + 4);
    uint4 hv, lv; split8(x, hv, lv);
    *(uint4*)(dh + 8*(size_t)i) = hv;
    *(uint4*)(dl + 8*(size_t)i) = lv;
}

// ---------------- router GEMM ----------------
__global__ void router_gemm(const float* __restrict__ xr, const float* __restrict__ wr,
                            float* __restrict__ logits) {
    __shared__ float Xs[16][68];
    __shared__ float Ws[16][36];
    int tid = threadIdx.x;
    int t0  = blockIdx.x * 64;
    int tx = tid & 31, ty = tid >> 5;
    float acc[8];
#pragma unroll
    for (int j = 0; j < 8; j++) acc[j] = 0.f;
    int mL = tid >> 2, ksL = tid & 3;
    for (int k0 = 0; k0 < HDIM; k0 += 16) {
        float4 v = *(const float4*)(xr + (size_t)(t0 + mL) * HDIM + k0 + ksL * 4);
        Xs[ksL*4+0][mL] = v.x; Xs[ksL*4+1][mL] = v.y;
        Xs[ksL*4+2][mL] = v.z; Xs[ksL*4+3][mL] = v.w;
        if (tid < 128) {
            int n = tid >> 2, ks = tid & 3;
            float4 w = *(const float4*)(wr + (size_t)n * HDIM + k0 + ks * 4);
            Ws[ks*4+0][n] = w.x; Ws[ks*4+1][n] = w.y;
            Ws[ks*4+2][n] = w.z; Ws[ks*4+3][n] = w.w;
        }
        __syncthreads();
#pragma unroll
        for (int kk = 0; kk < 16; kk++) {
            float b = Ws[kk][tx];
            float4 a0 = *(const float4*)&Xs[kk][ty*8];
            float4 a1 = *(const float4*)&Xs[kk][ty*8+4];
            acc[0] += a0.x*b; acc[1] += a0.y*b; acc[2] += a0.z*b; acc[3] += a0.w*b;
            acc[4] += a1.x*b; acc[5] += a1.y*b; acc[6] += a1.z*b; acc[7] += a1.w*b;
        }
        __syncthreads();
    }
#pragma unroll
    for (int j = 0; j < 8; j++)
        logits[(size_t)(t0 + ty*8 + j) * NE + tx] = acc[j];
}

__global__ void zero_cnt() { if (threadIdx.x < NE) g_cnt[threadIdx.x] = 0; }

__global__ void topk_kernel(const float* __restrict__ logits) {
    int t = blockIdx.x * blockDim.x + threadIdx.x;
    if (t >= T_TOK) return;
    float v[NE];
#pragma unroll
    for (int e = 0; e < NE; e++) v[e] = logits[(size_t)t * NE + e];
    float val[TOPK]; int sel[TOPK];
#pragma unroll
    for (int kk = 0; kk < TOPK; kk++) {
        float best = -INFINITY; int bi = 0;
#pragma unroll
        for (int e = 0; e < NE; e++)
            if (v[e] > best) { best = v[e]; bi = e; }
        val[kk] = best; sel[kk] = bi; v[bi] = -INFINITY;
    }
    float mx = val[0];
    float w[TOPK], s = 0.f;
#pragma unroll
    for (int kk = 0; kk < TOPK; kk++) { w[kk] = expf(val[kk] - mx); s += w[kk]; }
    float inv = 1.f / s;
#pragma unroll
    for (int kk = 0; kk < TOPK; kk++) {
        int e = sel[kk];
        int pos = atomicAdd(&g_cnt[e], 1);
        g_btok[e * T_TOK + pos] = t;
        g_bw  [e * T_TOK + pos] = w[kk] * inv;
        g_pe[t * TOPK + kk] = e;
        g_pp[t * TOPK + kk] = pos;
    }
}

__global__ void prefix_kernel() {
    if (threadIdx.x == 0) {
        int s = 0;
        for (int e = 0; e < NE; e++) { g_base[e] = s; s += g_cnt[e]; }
    }
}

// ================= gate/up HMMA kernel =================
// CTA: 128 tokens x 64 F-cols. 8 warps: wm = wid&3 (M), wn = wid>>2 (N), 32x32 warp tile.
// BK=32. X loaded pre-split bf16 (g_xh/g_xl); W converted in-kernel (multiplicity ~2).
#define PADK 40
__global__ void __launch_bounds__(256) gateup_mma(
        const float* __restrict__ wg, const float* __restrict__ wu) {
    int e   = blockIdx.z;
    int cnt = g_cnt[e];
    int m0  = blockIdx.y * 128;
    if (m0 >= cnt) return;
    int f0 = blockIdx.x * 64;

    __shared__ __nv_bfloat16 sXh[128][PADK], sXl[128][PADK];
    __shared__ __nv_bfloat16 sGh[64][PADK],  sGl[64][PADK];
    __shared__ __nv_bfloat16 sUh[64][PADK],  sUl[64][PADK];

    int tid = threadIdx.x, wid = tid >> 5, lane = tid & 31;
    int wm = wid & 3, wn = wid >> 2;
    int g = lane >> 2, q = lane & 3;

    // loader roles
    int xrow = tid >> 1, xseg = tid & 1;                 // X: 128 rows, 2 segs of 16 bf16
    int tokL = g_btok[e * T_TOK + min(m0 + xrow, cnt - 1)];
    const __nv_bfloat16* xhs = g_xh + (size_t)tokL * HDIM;
    const __nv_bfloat16* xls = g_xl + (size_t)tokL * HDIM;
    int wrow = tid >> 2, wq = tid & 3;                   // W: 64 rows, 4 segs of 8 fp32
    const float* gsrc = wg + (size_t)e * FDIM * HDIM + (size_t)(f0 + wrow) * HDIM;
    const float* usrc = wu + (size_t)e * FDIM * HDIM + (size_t)(f0 + wrow) * HDIM;

    float accG[2][4][4] = {}, accU[2][4][4] = {};

    for (int k0 = 0; k0 < HDIM; k0 += 32) {
        // --- stage: X direct bf16, W convert ---
        {
            int c = k0 + xseg * 16;
            *(uint4*)&sXh[xrow][xseg*16]   = *(const uint4*)(xhs + c);
            *(uint4*)&sXh[xrow][xseg*16+8] = *(const uint4*)(xhs + c + 8);
            *(uint4*)&sXl[xrow][xseg*16]   = *(const uint4*)(xls + c);
            *(uint4*)&sXl[xrow][xseg*16+8] = *(const uint4*)(xls + c + 8);
        }
        {
            float x[8]; uint4 hv, lv;
            const float* s = gsrc + k0 + wq * 8;
            *(float4*)&x[0] = *(const float4*)(s);
            *(float4*)&x[4] = *(const float4*)(s + 4);
            split8(x, hv, lv);
            *(uint4*)&sGh[wrow][wq*8] = hv;
            *(uint4*)&sGl[wrow][wq*8] = lv;
            s = usrc + k0 + wq * 8;
            *(float4*)&x[0] = *(const float4*)(s);
            *(float4*)&x[4] = *(const float4*)(s + 4);
            split8(x, hv, lv);
            *(uint4*)&sUh[wrow][wq*8] = hv;
            *(uint4*)&sUl[wrow][wq*8] = lv;
        }
        __syncthreads();

        // --- compute ---
#pragma unroll
        for (int kt = 0; kt < 2; kt++) {
            int kc = kt * 16 + 2 * q;
            uint32_t axh[2][4], axl[2][4];
#pragma unroll
            for (int mt = 0; mt < 2; mt++) {
                int r = wm * 32 + mt * 16 + g;
                axh[mt][0] = *(const uint32_t*)&sXh[r][kc];
                axh[mt][1] = *(const uint32_t*)&sXh[r+8][kc];
                axh[mt][2] = *(const uint32_t*)&sXh[r][kc+8];
                axh[mt][3] = *(const uint32_t*)&sXh[r+8][kc+8];
                axl[mt][0] = *(const uint32_t*)&sXl[r][kc];
                axl[mt][1] = *(const uint32_t*)&sXl[r+8][kc];
                axl[mt][2] = *(const uint32_t*)&sXl[r][kc+8];
                axl[mt][3] = *(const uint32_t*)&sXl[r+8][kc+8];
            }
#pragma unroll
            for (int nt = 0; nt < 4; nt++) {
                int br = wn * 32 + nt * 8 + g;
                uint32_t bgh[2] = {*(const uint32_t*)&sGh[br][kc], *(const uint32_t*)&sGh[br][kc+8]};
                uint32_t bgl[2] = {*(const uint32_t*)&sGl[br][kc], *(const uint32_t*)&sGl[br][kc+8]};
                uint32_t buh[2] = {*(const uint32_t*)&sUh[br][kc], *(const uint32_t*)&sUh[br][kc+8]};
                uint32_t bul[2] = {*(const uint32_t*)&sUl[br][kc], *(const uint32_t*)&sUl[br][kc+8]};
#pragma unroll
                for (int mt = 0; mt < 2; mt++) {
                    mma16816(accG[mt][nt], axh[mt], bgh);
                    mma16816(accG[mt][nt], axl[mt], bgh);
                    mma16816(accG[mt][nt], axh[mt], bgl);
                    mma16816(accU[mt][nt], axh[mt], buh);
                    mma16816(accU[mt][nt], axl[mt], buh);
                    mma16816(accU[mt][nt], axh[mt], bul);
                }
            }
        }
        __syncthreads();
    }

    // --- epilogue: h = relu(G)*U, write bf16 hi/lo ---
    int base = g_base[e];
#pragma unroll
    for (int mt = 0; mt < 2; mt++) {
        int lm0 = wm * 32 + mt * 16 + g;
#pragma unroll
        for (int nt = 0; nt < 4; nt++) {
            int c = f0 + wn * 32 + nt * 8 + 2 * q;
            float* Gd = accG[mt][nt];
            float* Ud = accU[mt][nt];
            float v0 = fmaxf(Gd[0], 0.f) * Ud[0];
            float v1 = fmaxf(Gd[1], 0.f) * Ud[1];
            float v2 = fmaxf(Gd[2], 0.f) * Ud[2];
            float v3 = fmaxf(Gd[3], 0.f) * Ud[3];
            uint32_t h01, l01, h23, l23;
            split2(v0, v1, h01, l01);
            split2(v2, v3, h23, l23);
            int m = m0 + lm0;
            if (m < cnt) {
                size_t slot = (size_t)base + m;
                *(uint32_t*)(g_hhi + slot * FDIM + c) = h01;
                *(uint32_t*)(g_hlo + slot * FDIM + c) = l01;
            }
            if (m + 8 < cnt) {
                size_t slot = (size_t)base + m + 8;
                *(uint32_t*)(g_hhi + slot * FDIM + c) = h23;
                *(uint32_t*)(g_hlo + slot * FDIM + c) = l23;
            }
        }
    }
}

// ================= down HMMA kernel =================
// CTA: 128 slots x 64 H-cols, K=FDIM in 16 chunks of 32.
__global__ void __launch_bounds__(256) down_mma(const float* __restrict__ wd) {
    int e   = blockIdx.z;
    int cnt = g_cnt[e];
    int m0  = blockIdx.y * 128;
    if (m0 >= cnt) return;
    int h0 = blockIdx.x * 64;

    __shared__ __nv_bfloat16 sXh[128][PADK], sXl[128][PADK];
    __shared__ __nv_bfloat16 sWh[64][PADK],  sWl[64][PADK];

    int tid = threadIdx.x, wid = tid >> 5, lane = tid & 31;
    int wm = wid & 3, wn = wid >> 2;
    int g = lane >> 2, q = lane & 3;
    int base = g_base[e];

    int xrow = tid >> 1, xseg = tid & 1;
    size_t slotR = (size_t)base + min(m0 + xrow, cnt - 1);
    const __nv_bfloat16* xhs = g_hhi + slotR * FDIM;
    const __nv_bfloat16* xls = g_hlo + slotR * FDIM;
    int wrow = tid >> 2, wq = tid & 3;
    const float* wsrc = wd + (size_t)e * HDIM * FDIM + (size_t)(h0 + wrow) * FDIM;

    float acc[2][4][4] = {};

    for (int k0 = 0; k0 < FDIM; k0 += 32) {
        {
            int c = k0 + xseg * 16;
            *(uint4*)&sXh[xrow][xseg*16]   = *(const uint4*)(xhs + c);
            *(uint4*)&sXh[xrow][xseg*16+8] = *(const uint4*)(xhs + c + 8);
            *(uint4*)&sXl[xrow][xseg*16]   = *(const uint4*)(xls + c);
            *(uint4*)&sXl[xrow][xseg*16+8] = *(const uint4*)(xls + c + 8);
        }
        {
            float x[8]; uint4 hv, lv;
            const float* s = wsrc + k0 + wq * 8;
            *(float4*)&x[0] = *(const float4*)(s);
            *(float4*)&x[4] = *(const float4*)(s + 4);
            split8(x, hv, lv);
            *(uint4*)&sWh[wrow][wq*8] = hv;
            *(uint4*)&sWl[wrow][wq*8] = lv;
        }
        __syncthreads();

#pragma unroll
        for (int kt = 0; kt < 2; kt++) {
            int kc = kt * 16 + 2 * q;
            uint32_t axh[2][4], axl[2][4];
#pragma unroll
            for (int mt = 0; mt < 2; mt++) {
                int r = wm * 32 + mt * 16 + g;
                axh[mt][0] = *(const uint32_t*)&sXh[r][kc];
                axh[mt][1] = *(const uint32_t*)&sXh[r+8][kc];
                axh[mt][2] = *(const uint32_t*)&sXh[r][kc+8];
                axh[mt][3] = *(const uint32_t*)&sXh[r+8][kc+8];
                axl[mt][0] = *(const uint32_t*)&sXl[r][kc];
                axl[mt][1] = *(const uint32_t*)&sXl[r+8][kc];
                axl[mt][2] = *(const uint32_t*)&sXl[r][kc+8];
                axl[mt][3] = *(const uint32_t*)&sXl[r+8][kc+8];
            }
#pragma unroll
            for (int nt = 0; nt < 4; nt++) {
                int br = wn * 32 + nt * 8 + g;
                uint32_t bwh[2] = {*(const uint32_t*)&sWh[br][kc], *(const uint32_t*)&sWh[br][kc+8]};
                uint32_t bwl[2] = {*(const uint32_t*)&sWl[br][kc], *(const uint32_t*)&sWl[br][kc+8]};
#pragma unroll
                for (int mt = 0; mt < 2; mt++) {
                    mma16816(acc[mt][nt], axh[mt], bwh);
                    mma16816(acc[mt][nt], axl[mt], bwh);
                    mma16816(acc[mt][nt], axh[mt], bwl);
                }
            }
        }
        __syncthreads();
    }

    // --- epilogue: y = acc * routing weight ---
#pragma unroll
    for (int mt = 0; mt < 2; mt++) {
        int lm0 = wm * 32 + mt * 16 + g;
        int m = m0 + lm0;
        float w0 = (m     < cnt) ? g_bw[e * T_TOK + m]     : 0.f;
        float w1 = (m + 8 < cnt) ? g_bw[e * T_TOK + m + 8] : 0.f;
#pragma unroll
        for (int nt = 0; nt < 4; nt++) {
            int c = h0 + wn * 32 + nt * 8 + 2 * q;
            float* D = acc[mt][nt];
            if (m < cnt) {
                float* py = g_ybuf + ((size_t)base + m) * HDIM + c;
                py[0] = D[0] * w0; py[1] = D[1] * w0;
            }
            if (m + 8 < cnt) {
                float* py = g_ybuf + ((size_t)base + m + 8) * HDIM + c;
                py[0] = D[2] * w1; py[1] = D[3] * w1;
            }
        }
    }
}

// ---------------- combine ----------------
__global__ void combine_kernel(float* __restrict__ out) {
    int t   = blockIdx.x;
    int tid = threadIdx.x;
    int sl[TOPK];
#pragma unroll
    for (int kk = 0; kk < TOPK; kk++)
        sl[kk] = g_base[g_pe[t*TOPK + kk]] + g_pp[t*TOPK + kk];
    int h = tid * 4;
    float4 a = *(const float4*)(g_ybuf + (size_t)sl[0] * HDIM + h);
    float4 b = *(const float4*)(g_ybuf + (size_t)sl[1] * HDIM + h);
    float4 c = *(const float4*)(g_ybuf + (size_t)sl[2] * HDIM + h);
    float4 d = *(const float4*)(g_ybuf + (size_t)sl[3] * HDIM + h);
    float4 r;
    r.x = a.x + b.x + c.x + d.x;
    r.y = a.y + b.y + c.y + d.y;
    r.z = a.z + b.z + c.z + d.z;
    r.w = a.w + b.w + c.w + d.w;
    *(float4*)(out + (size_t)t * HDIM + h) = r;
}

// ---------------- launch ----------------
extern "C" void kernel_launch(void* const* d_in, const int* in_sizes, int n_in,
                              void* d_out, int out_size) {
    const float* router_input = (const float*)d_in[0];
    const float* hidden       = (const float*)d_in[1];
    const float* w_router     = (const float*)d_in[2];
    const float* w_gate       = (const float*)d_in[3];
    const float* w_up         = (const float*)d_in[4];
    const float* w_down       = (const float*)d_in[5];
    float* out    = (float*)d_out;
    float* logits = out + (size_t)T_TOK * HDIM;

    __nv_bfloat16 *xh, *xl;
    cudaGetSymbolAddress((void**)&xh, g_xh);
    cudaGetSymbolAddress((void**)&xl, g_xl);

    const int XN8 = T_TOK * HDIM / 8;
    convert_split<<<XN8 / 256, 256>>>(hidden, xh, xl, XN8);

    zero_cnt<<<1, 32>>>();
    router_gemm<<<T_TOK / 64, 256>>>(router_input, w_router, logits);
    topk_kernel<<<T_TOK / 256, 256>>>(logits);
    prefix_kernel<<<1, 32>>>();
    gateup_mma<<<dim3(FDIM / 64, T_TOK / 128, NE), 256>>>(w_gate, w_up);
    down_mma<<<dim3(HDIM / 64, T_TOK / 128, NE), 256>>>(w_down);
    combine_kernel<<<T_TOK, 256>>>(out);
}

// round 9
// speedup vs baseline: 1.1902x; 1.0221x over previous
#include <cuda_runtime.h>
#include <cuda_bf16.h>
#include <math.h>
#include <stdint.h>

#define T_TOK 2048
#define HDIM  1024
#define FDIM  512
#define NE    32
#define TOPK  4
#define SLOTS (T_TOK * TOPK)

// ---------------- scratch ----------------
__device__ int   g_cnt[NE];
__device__ int   g_base[NE];
__device__ int   g_btok[NE * T_TOK];
__device__ float g_bw  [NE * T_TOK];
__device__ int   g_pe  [T_TOK * TOPK];
__device__ int   g_pp  [T_TOK * TOPK];
__device__ __nv_bfloat16 g_hhi[(size_t)SLOTS * FDIM];   // 8 MB
__device__ __nv_bfloat16 g_hlo[(size_t)SLOTS * FDIM];   // 8 MB
__device__ float g_ybuf[(size_t)SLOTS * HDIM];          // 32 MB

// ---------------- helpers ----------------
__device__ __forceinline__ void mma16816(float* d, const uint32_t* a, const uint32_t* b) {
    asm volatile(
        "mma.sync.aligned.m16n8k16.row.col.f32.bf16.bf16.f32 "
        "{%0,%1,%2,%3}, {%4,%5,%6,%7}, {%8,%9}, {%0,%1,%2,%3};\n"
        : "+f"(d[0]), "+f"(d[1]), "+f"(d[2]), "+f"(d[3])
        : "r"(a[0]), "r"(a[1]), "r"(a[2]), "r"(a[3]), "r"(b[0]), "r"(b[1]));
}

__device__ __forceinline__ void ldm4(uint32_t* r, uint32_t a) {
    asm volatile("ldmatrix.sync.aligned.m8n8.x4.shared.b16 {%0,%1,%2,%3}, [%4];"
        : "=r"(r[0]), "=r"(r[1]), "=r"(r[2]), "=r"(r[3]) : "r"(a));
}

__device__ __forceinline__ uint32_t smem_u32(const void* p) {
    uint32_t a;
    asm("{ .reg .u64 t; cvta.to.shared.u64 t, %1; cvt.u32.u64 %0, t; }" : "=r"(a) : "l"(p));
    return a;
}

__device__ __forceinline__ void split2(float a, float b, uint32_t& h, uint32_t& l) {
    __nv_bfloat162 hh = __floats2bfloat162_rn(a, b);
    float2 hf = __bfloat1622float2(hh);
    __nv_bfloat162 ll = __floats2bfloat162_rn(a - hf.x, b - hf.y);
    h = *reinterpret_cast<uint32_t*>(&hh);
    l = *reinterpret_cast<uint32_t*>(&ll);
}

__device__ __forceinline__ void split8(const float* x, uint4& hv, uint4& lv) {
    uint32_t h[4], l[4];
#pragma unroll
    for (int i = 0; i < 4; i++) split2(x[2*i], x[2*i+1], h[i], l[i]);
    hv = make_uint4(h[0], h[1], h[2], h[3]);
    lv = make_uint4(l[0], l[1], l[2], l[3]);
}

// ---------------- router GEMM ----------------
__global__ void router_gemm(const float* __restrict__ xr, const float* __restrict__ wr,
                            float* __restrict__ logits) {
    __shared__ float Xs[16][68];
    __shared__ float Ws[16][36];
    int tid = threadIdx.x;
    int t0  = blockIdx.x * 64;
    int tx = tid & 31, ty = tid >> 5;
    float acc[8];
#pragma unroll
    for (int j = 0; j < 8; j++) acc[j] = 0.f;
    int mL = tid >> 2, ksL = tid & 3;
    for (int k0 = 0; k0 < HDIM; k0 += 16) {
        float4 v = *(const float4*)(xr + (size_t)(t0 + mL) * HDIM + k0 + ksL * 4);
        Xs[ksL*4+0][mL] = v.x; Xs[ksL*4+1][mL] = v.y;
        Xs[ksL*4+2][mL] = v.z; Xs[ksL*4+3][mL] = v.w;
        if (tid < 128) {
            int n = tid >> 2, ks = tid & 3;
            float4 w = *(const float4*)(wr + (size_t)n * HDIM + k0 + ks * 4);
            Ws[ks*4+0][n] = w.x; Ws[ks*4+1][n] = w.y;
            Ws[ks*4+2][n] = w.z; Ws[ks*4+3][n] = w.w;
        }
        __syncthreads();
#pragma unroll
        for (int kk = 0; kk < 16; kk++) {
            float b = Ws[kk][tx];
            float4 a0 = *(const float4*)&Xs[kk][ty*8];
            float4 a1 = *(const float4*)&Xs[kk][ty*8+4];
            acc[0] += a0.x*b; acc[1] += a0.y*b; acc[2] += a0.z*b; acc[3] += a0.w*b;
            acc[4] += a1.x*b; acc[5] += a1.y*b; acc[6] += a1.z*b; acc[7] += a1.w*b;
        }
        __syncthreads();
    }
#pragma unroll
    for (int j = 0; j < 8; j++)
        logits[(size_t)(t0 + ty*8 + j) * NE + tx] = acc[j];
}

__global__ void zero_cnt() { if (threadIdx.x < NE) g_cnt[threadIdx.x] = 0; }

__global__ void topk_kernel(const float* __restrict__ logits) {
    int t = blockIdx.x * blockDim.x + threadIdx.x;
    if (t >= T_TOK) return;
    float v[NE];
#pragma unroll
    for (int e = 0; e < NE; e++) v[e] = logits[(size_t)t * NE + e];
    float val[TOPK]; int sel[TOPK];
#pragma unroll
    for (int kk = 0; kk < TOPK; kk++) {
        float best = -INFINITY; int bi = 0;
#pragma unroll
        for (int e = 0; e < NE; e++)
            if (v[e] > best) { best = v[e]; bi = e; }
        val[kk] = best; sel[kk] = bi; v[bi] = -INFINITY;
    }
    float mx = val[0];
    float w[TOPK], s = 0.f;
#pragma unroll
    for (int kk = 0; kk < TOPK; kk++) { w[kk] = expf(val[kk] - mx); s += w[kk]; }
    float inv = 1.f / s;
#pragma unroll
    for (int kk = 0; kk < TOPK; kk++) {
        int e = sel[kk];
        int pos = atomicAdd(&g_cnt[e], 1);
        g_btok[e * T_TOK + pos] = t;
        g_bw  [e * T_TOK + pos] = w[kk] * inv;
        g_pe[t * TOPK + kk] = e;
        g_pp[t * TOPK + kk] = pos;
    }
}

__global__ void prefix_kernel() {
    if (threadIdx.x == 0) {
        int s = 0;
        for (int e = 0; e < NE; e++) { g_base[e] = s; s += g_cnt[e]; }
    }
}

// ================= gate/up HMMA kernel (ldmatrix fragments) =================
// CTA: 128 tokens x 64 F-cols, 8 warps (wm=wid&3, wn=wid>>2), 32x32 warp tiles, BK=32.
#define PADK 40
__global__ void __launch_bounds__(256, 2) gateup_mma(
        const float* __restrict__ hid, const float* __restrict__ wg,
        const float* __restrict__ wu) {
    int e   = blockIdx.z;
    int cnt = g_cnt[e];
    int m0  = blockIdx.y * 128;
    if (m0 >= cnt) return;
    int f0 = blockIdx.x * 64;

    __shared__ __nv_bfloat16 sXh[128][PADK], sXl[128][PADK];
    __shared__ __nv_bfloat16 sGh[64][PADK],  sGl[64][PADK];
    __shared__ __nv_bfloat16 sUh[64][PADK],  sUl[64][PADK];

    int tid = threadIdx.x, wid = tid >> 5, lane = tid & 31;
    int wm = wid & 3, wn = wid >> 2;
    int g = lane >> 2, q = lane & 3;

    // loader roles (identical to R4)
    int xrow = tid >> 1, xseg = tid & 1;
    int tokL = g_btok[e * T_TOK + min(m0 + xrow, cnt - 1)];
    const float* xsrc = hid + (size_t)tokL * HDIM;
    int wrow = tid >> 2, wq = tid & 3;
    const float* gsrc = wg + (size_t)e * FDIM * HDIM + (size_t)(f0 + wrow) * HDIM;
    const float* usrc = wu + (size_t)e * FDIM * HDIM + (size_t)(f0 + wrow) * HDIM;

    // ldmatrix lane addresses
    // A (16x16 tile, x4): row = base + (lane&15), col-16B-half = (lane>>4)&1
    uint32_t aXh = smem_u32(&sXh[0][0]) + (uint32_t)(((wm*32 + (lane & 15)) * PADK + ((lane >> 4) & 1) * 8) * 2);
    uint32_t aXl = smem_u32(&sXl[0][0]) + (uint32_t)(((wm*32 + (lane & 15)) * PADK + ((lane >> 4) & 1) * 8) * 2);
    // B (two 8-row nt tiles per x4): rows 0-7 -> nt even @kc, 8-15 -> nt even @kc+8,
    // 16-23 -> nt odd @kc, 24-31 -> nt odd @kc+8
    uint32_t boff = (uint32_t)(((wn*32 + ((lane >> 4) & 1) * 8 + (lane & 7)) * PADK + ((lane >> 3) & 1) * 8) * 2);
    uint32_t aGh = smem_u32(&sGh[0][0]) + boff;
    uint32_t aGl = smem_u32(&sGl[0][0]) + boff;
    uint32_t aUh = smem_u32(&sUh[0][0]) + boff;
    uint32_t aUl = smem_u32(&sUl[0][0]) + boff;
    const uint32_t MT_STRIDE = 16 * PADK * 2;   // 1280 bytes (16 rows)

    float accG[2][4][4] = {}, accU[2][4][4] = {};

    for (int k0 = 0; k0 < HDIM; k0 += 32) {
        // --- stage + convert (identical to R4) ---
        {
            const float* s = xsrc + k0 + xseg * 16;
            float x[8]; uint4 hv, lv;
            *(float4*)&x[0] = *(const float4*)(s);
            *(float4*)&x[4] = *(const float4*)(s + 4);
            split8(x, hv, lv);
            *(uint4*)&sXh[xrow][xseg*16]   = hv;
            *(uint4*)&sXl[xrow][xseg*16]   = lv;
            *(float4*)&x[0] = *(const float4*)(s + 8);
            *(float4*)&x[4] = *(const float4*)(s + 12);
            split8(x, hv, lv);
            *(uint4*)&sXh[xrow][xseg*16+8] = hv;
            *(uint4*)&sXl[xrow][xseg*16+8] = lv;
        }
        {
            float x[8]; uint4 hv, lv;
            const float* s = gsrc + k0 + wq * 8;
            *(float4*)&x[0] = *(const float4*)(s);
            *(float4*)&x[4] = *(const float4*)(s + 4);
            split8(x, hv, lv);
            *(uint4*)&sGh[wrow][wq*8] = hv;
            *(uint4*)&sGl[wrow][wq*8] = lv;
            s = usrc + k0 + wq * 8;
            *(float4*)&x[0] = *(const float4*)(s);
            *(float4*)&x[4] = *(const float4*)(s + 4);
            split8(x, hv, lv);
            *(uint4*)&sUh[wrow][wq*8] = hv;
            *(uint4*)&sUl[wrow][wq*8] = lv;
        }
        __syncthreads();

        // --- compute via ldmatrix ---
#pragma unroll
        for (int kt = 0; kt < 2; kt++) {
            uint32_t kadd = (uint32_t)kt * 32;
            uint32_t axh[2][4], axl[2][4];
            ldm4(axh[0], aXh + kadd);
            ldm4(axh[1], aXh + MT_STRIDE + kadd);
            ldm4(axl[0], aXl + kadd);
            ldm4(axl[1], aXl + MT_STRIDE + kadd);
#pragma unroll
            for (int p = 0; p < 2; p++) {
                uint32_t padd = (uint32_t)p * MT_STRIDE + kadd;
                uint32_t bgh[4], bgl[4], buh[4], bul[4];
                ldm4(bgh, aGh + padd);
                ldm4(bgl, aGl + padd);
                ldm4(buh, aUh + padd);
                ldm4(bul, aUl + padd);
#pragma unroll
                for (int j = 0; j < 2; j++) {
                    int nt = 2*p + j;
#pragma unroll
                    for (int mt = 0; mt < 2; mt++) {
                        mma16816(accG[mt][nt], axh[mt], &bgh[2*j]);
                        mma16816(accG[mt][nt], axl[mt], &bgh[2*j]);
                        mma16816(accG[mt][nt], axh[mt], &bgl[2*j]);
                        mma16816(accU[mt][nt], axh[mt], &buh[2*j]);
                        mma16816(accU[mt][nt], axl[mt], &buh[2*j]);
                        mma16816(accU[mt][nt], axh[mt], &bul[2*j]);
                    }
                }
            }
        }
        __syncthreads();
    }

    // --- epilogue: h = relu(G)*U, write bf16 hi/lo (identical to R4) ---
    int base = g_base[e];
#pragma unroll
    for (int mt = 0; mt < 2; mt++) {
        int lm0 = wm * 32 + mt * 16 + g;
#pragma unroll
        for (int nt = 0; nt < 4; nt++) {
            int c = f0 + wn * 32 + nt * 8 + 2 * q;
            float* Gd = accG[mt][nt];
            float* Ud = accU[mt][nt];
            float v0 = fmaxf(Gd[0], 0.f) * Ud[0];
            float v1 = fmaxf(Gd[1], 0.f) * Ud[1];
            float v2 = fmaxf(Gd[2], 0.f) * Ud[2];
            float v3 = fmaxf(Gd[3], 0.f) * Ud[3];
            uint32_t h01, l01, h23, l23;
            split2(v0, v1, h01, l01);
            split2(v2, v3, h23, l23);
            int m = m0 + lm0;
            if (m < cnt) {
                size_t slot = (size_t)base + m;
                *(uint32_t*)(g_hhi + slot * FDIM + c) = h01;
                *(uint32_t*)(g_hlo + slot * FDIM + c) = l01;
            }
            if (m + 8 < cnt) {
                size_t slot = (size_t)base + m + 8;
                *(uint32_t*)(g_hhi + slot * FDIM + c) = h23;
                *(uint32_t*)(g_hlo + slot * FDIM + c) = l23;
            }
        }
    }
}

// ================= down HMMA kernel (ldmatrix fragments) =================
__global__ void __launch_bounds__(256, 2) down_mma(const float* __restrict__ wd) {
    int e   = blockIdx.z;
    int cnt = g_cnt[e];
    int m0  = blockIdx.y * 128;
    if (m0 >= cnt) return;
    int h0 = blockIdx.x * 64;

    __shared__ __nv_bfloat16 sXh[128][PADK], sXl[128][PADK];
    __shared__ __nv_bfloat16 sWh[64][PADK],  sWl[64][PADK];

    int tid = threadIdx.x, wid = tid >> 5, lane = tid & 31;
    int wm = wid & 3, wn = wid >> 2;
    int g = lane >> 2, q = lane & 3;
    int base = g_base[e];

    int xrow = tid >> 1, xseg = tid & 1;
    size_t slotR = (size_t)base + min(m0 + xrow, cnt - 1);
    const __nv_bfloat16* xhs = g_hhi + slotR * FDIM;
    const __nv_bfloat16* xls = g_hlo + slotR * FDIM;
    int wrow = tid >> 2, wq = tid & 3;
    const float* wsrc = wd + (size_t)e * HDIM * FDIM + (size_t)(h0 + wrow) * FDIM;

    uint32_t aXh = smem_u32(&sXh[0][0]) + (uint32_t)(((wm*32 + (lane & 15)) * PADK + ((lane >> 4) & 1) * 8) * 2);
    uint32_t aXl = smem_u32(&sXl[0][0]) + (uint32_t)(((wm*32 + (lane & 15)) * PADK + ((lane >> 4) & 1) * 8) * 2);
    uint32_t boff = (uint32_t)(((wn*32 + ((lane >> 4) & 1) * 8 + (lane & 7)) * PADK + ((lane >> 3) & 1) * 8) * 2);
    uint32_t aWh = smem_u32(&sWh[0][0]) + boff;
    uint32_t aWl = smem_u32(&sWl[0][0]) + boff;
    const uint32_t MT_STRIDE = 16 * PADK * 2;

    float acc[2][4][4] = {};

    for (int k0 = 0; k0 < FDIM; k0 += 32) {
        {
            int c = k0 + xseg * 16;
            *(uint4*)&sXh[xrow][xseg*16]   = *(const uint4*)(xhs + c);
            *(uint4*)&sXh[xrow][xseg*16+8] = *(const uint4*)(xhs + c + 8);
            *(uint4*)&sXl[xrow][xseg*16]   = *(const uint4*)(xls + c);
            *(uint4*)&sXl[xrow][xseg*16+8] = *(const uint4*)(xls + c + 8);
        }
        {
            float x[8]; uint4 hv, lv;
            const float* s = wsrc + k0 + wq * 8;
            *(float4*)&x[0] = *(const float4*)(s);
            *(float4*)&x[4] = *(const float4*)(s + 4);
            split8(x, hv, lv);
            *(uint4*)&sWh[wrow][wq*8] = hv;
            *(uint4*)&sWl[wrow][wq*8] = lv;
        }
        __syncthreads();

#pragma unroll
        for (int kt = 0; kt < 2; kt++) {
            uint32_t kadd = (uint32_t)kt * 32;
            uint32_t axh[2][4], axl[2][4];
            ldm4(axh[0], aXh + kadd);
            ldm4(axh[1], aXh + MT_STRIDE + kadd);
            ldm4(axl[0], aXl + kadd);
            ldm4(axl[1], aXl + MT_STRIDE + kadd);
#pragma unroll
            for (int p = 0; p < 2; p++) {
                uint32_t padd = (uint32_t)p * MT_STRIDE + kadd;
                uint32_t bwh[4], bwl[4];
                ldm4(bwh, aWh + padd);
                ldm4(bwl, aWl + padd);
#pragma unroll
                for (int j = 0; j < 2; j++) {
                    int nt = 2*p + j;
#pragma unroll
                    for (int mt = 0; mt < 2; mt++) {
                        mma16816(acc[mt][nt], axh[mt], &bwh[2*j]);
                        mma16816(acc[mt][nt], axl[mt], &bwh[2*j]);
                        mma16816(acc[mt][nt], axh[mt], &bwl[2*j]);
                    }
                }
            }
        }
        __syncthreads();
    }

    // --- epilogue: y = acc * routing weight (identical to R4) ---
#pragma unroll
    for (int mt = 0; mt < 2; mt++) {
        int lm0 = wm * 32 + mt * 16 + g;
        int m = m0 + lm0;
        float w0 = (m     < cnt) ? g_bw[e * T_TOK + m]     : 0.f;
        float w1 = (m + 8 < cnt) ? g_bw[e * T_TOK + m + 8] : 0.f;
#pragma unroll
        for (int nt = 0; nt < 4; nt++) {
            int c = h0 + wn * 32 + nt * 8 + 2 * q;
            float* D = acc[mt][nt];
            if (m < cnt) {
                float* py = g_ybuf + ((size_t)base + m) * HDIM + c;
                py[0] = D[0] * w0; py[1] = D[1] * w0;
            }
            if (m + 8 < cnt) {
                float* py = g_ybuf + ((size_t)base + m + 8) * HDIM + c;
                py[0] = D[2] * w1; py[1] = D[3] * w1;
            }
        }
    }
}

// ---------------- combine ----------------
__global__ void combine_kernel(float* __restrict__ out) {
    int t   = blockIdx.x;
    int tid = threadIdx.x;
    int sl[TOPK];
#pragma unroll
    for (int kk = 0; kk < TOPK; kk++)
        sl[kk] = g_base[g_pe[t*TOPK + kk]] + g_pp[t*TOPK + kk];
    int h = tid * 4;
    float4 a = *(const float4*)(g_ybuf + (size_t)sl[0] * HDIM + h);
    float4 b = *(const float4*)(g_ybuf + (size_t)sl[1] * HDIM + h);
    float4 c = *(const float4*)(g_ybuf + (size_t)sl[2] * HDIM + h);
    float4 d = *(const float4*)(g_ybuf + (size_t)sl[3] * HDIM + h);
    float4 r;
    r.x = a.x + b.x + c.x + d.x;
    r.y = a.y + b.y + c.y + d.y;
    r.z = a.z + b.z + c.z + d.z;
    r.w = a.w + b.w + c.w + d.w;
    *(float4*)(out + (size_t)t * HDIM + h) = r;
}

// ---------------- launch ----------------
extern "C" void kernel_launch(void* const* d_in, const int* in_sizes, int n_in,
                              void* d_out, int out_size) {
    const float* router_input = (const float*)d_in[0];
    const float* hidden       = (const float*)d_in[1];
    const float* w_router     = (const float*)d_in[2];
    const float* w_gate       = (const float*)d_in[3];
    const float* w_up         = (const float*)d_in[4];
    const float* w_down       = (const float*)d_in[5];
    float* out    = (float*)d_out;
    float* logits = out + (size_t)T_TOK * HDIM;

    zero_cnt<<<1, 32>>>();
    router_gemm<<<T_TOK / 64, 256>>>(router_input, w_router, logits);
    topk_kernel<<<T_TOK / 256, 256>>>(logits);
    prefix_kernel<<<1, 32>>>();
    gateup_mma<<<dim3(FDIM / 64, T_TOK / 128, NE), 256>>>(hidden, w_gate, w_up);
    down_mma<<<dim3(HDIM / 64, T_TOK / 128, NE), 256>>>(w_down);
    combine_kernel<<<T_TOK, 256>>>(out);
}